// round 15
// baseline (speedup 1.0000x reference)
#include <cuda_runtime.h>
#include <cstdint>
#include <cstddef>

// Problem constants
#define BB 16
#define CC 256
#define HH 64
#define WW 64
#define HW (HH*WW)
#define DD 4          // max displacement
#define PP 9          // patch = 2d+1

// Tiling
#define TI 4          // rows per block tile
#define KC 8          // channels per staged chunk
#define NCHUNK (CC/KC)
#define XS4 16        // x row stride in f4 slots (64 floats, XOR-closed group)
#define YR (TI + 2*DD)   // 12 y rows per tile
#define YS4 24        // y row stride in f4 slots (96 floats: 3 XOR groups)

#define NTH 288       // 9 warps; warp w == displacement row di
#define NBUF 2

#define XSZ4 (KC*TI*XS4)    // 512 f4
#define YSZ4 (KC*YR*YS4)    // 2304 f4
#define BUF4 (XSZ4+YSZ4)    // 2816 f4 = 45056 B
#define SMEM_BYTES (NBUF*BUF4*16)   // 90112 B; x2 blocks/SM = 176 KB

// Per-row XOR swizzle on 16B granularity; sw in {0,1,4,5}.
__device__ __forceinline__ int swz(int row) {
    return (row & 1) | ((row & 2) << 1);
}
// phys slot from logical slot l and row swizzle sw (XOR low 3 bits only)
__device__ __forceinline__ int psl(int l, int sw) {
    return (l & ~7) | ((l & 7) ^ sw);
}

__device__ __forceinline__ uint32_t s2u(const void* p) {
    return (uint32_t)__cvta_generic_to_shared(p);
}
__device__ __forceinline__ void cpa16(uint32_t s, const float* g) {
    asm volatile("cp.async.cg.shared.global [%0], [%1], 16;\n" :: "r"(s), "l"(g));
}
__device__ __forceinline__ void cp_commit() {
    asm volatile("cp.async.commit_group;\n");
}

// Stage one 8-channel chunk into buffer sb (f4 pointer). 16B .cg jobs only.
__device__ __forceinline__ void stage_chunk(float4* sb,
                                            const float* __restrict__ xb,
                                            const float* __restrict__ yb,
                                            int c0, int i0, int tid, int vmask)
{
    // x: KC*TI*16 = 512 f4 jobs; phys = psl(j4, swz(r))
    for (int idx = tid; idx < KC * TI * 16; idx += NTH) {
        int c  = idx >> 6;
        int rr = (idx >> 4) & 3;
        int j4 = idx & 15;
        uint32_t s = s2u(sb + c * (TI * XS4) + rr * XS4 + psl(j4, swz(rr)));
        cpa16(s, xb + (size_t)(c0 + c) * HW + (i0 + rr) * WW + j4 * 4);
    }
    // y: KC*YR*16 = 1536 f4 jobs; logical slot l = j4+1 (halo slot 0 stays 0)
    for (int idx = tid; idx < KC * YR * 16; idx += NTH) {
        int j4 = idx & 15;
        int c  = (idx >> 4) & 7;
        int q  = idx >> 7;
        if ((vmask >> q) & 1) {
            int gi = i0 + q - DD;
            uint32_t s = s2u(sb + XSZ4 + c * (YR * YS4) + q * YS4 +
                             psl(j4 + 1, swz(q & 3)));
            cpa16(s, yb + (size_t)(c0 + c) * HW + gi * WW + j4 * 4);
        }
    }
}

// Compute: 8 cols x 9 dj per thread; 2 x-LDS.128 + 4 y-LDS.128 per channel,
// 72 scalar FFMA. All smem offsets thread-constant (precomputed).
__device__ __forceinline__ void compute_chunk(const float4* sb, float acc[8][PP],
                                              int xo0, int xo1,
                                              int yo0, int yo1, int yo2, int yo3)
{
    const float4* X = sb;
    const float4* Y = sb + XSZ4;
    #pragma unroll
    for (int c = 0; c < KC; ++c) {
        float4 a0 = X[c * (TI * XS4) + xo0];
        float4 a1 = X[c * (TI * XS4) + xo1];
        float4 b0 = Y[c * (YR * YS4) + yo0];
        float4 b1 = Y[c * (YR * YS4) + yo1];
        float4 b2 = Y[c * (YR * YS4) + yo2];
        float4 b3 = Y[c * (YR * YS4) + yo3];

        float xv[8]  = {a0.x, a0.y, a0.z, a0.w, a1.x, a1.y, a1.z, a1.w};
        float yv[16] = {b0.x, b0.y, b0.z, b0.w, b1.x, b1.y, b1.z, b1.w,
                        b2.x, b2.y, b2.z, b2.w, b3.x, b3.y, b3.z, b3.w};
        #pragma unroll
        for (int k = 0; k < 8; ++k)
            #pragma unroll
            for (int d = 0; d < PP; ++d)
                acc[k][d] += xv[k] * yv[k + d];
    }
}

__global__ __launch_bounds__(NTH, 2)
void corr_kernel(const float* __restrict__ x,
                 const float* __restrict__ y,
                 float* __restrict__ out)
{
    extern __shared__ float4 smem[];   // [NBUF][BUF4]

    const int bx   = blockIdx.x;
    const int b    = bx >> 4;
    const int i0   = (bx & 15) * TI;
    const int tid  = threadIdx.x;
    const int di   = tid >> 5;
    const int lane = tid & 31;
    const int r    = lane & 3;
    const int q    = lane >> 2;           // jseg = 8q
    const int ry   = r + di;              // y row in padded tile
    const int jseg = q * 8;

    // Thread-constant swizzled f4 offsets (within one channel's region)
    const int swx = swz(r);
    const int swy = swz(ry & 3);
    const int xo0 = r * XS4 + psl(2 * q,     swx);
    const int xo1 = r * XS4 + psl(2 * q + 1, swx);
    const int yo0 = ry * YS4 + psl(2 * q,     swy);
    const int yo1 = ry * YS4 + psl(2 * q + 1, swy);
    const int yo2 = ry * YS4 + psl(2 * q + 2, swy);
    const int yo3 = ry * YS4 + psl(2 * q + 3, swy);

    const float* xb = x + (size_t)b * CC * HW;
    const float* yb = y + (size_t)b * CC * HW;

    // Valid-row mask for the y tile (rows i0-4 .. i0+7)
    int vmask = 0;
    #pragma unroll
    for (int qq = 0; qq < YR; ++qq) {
        int gi = i0 + qq - DD;
        if (gi >= 0 && gi < HH) vmask |= (1 << qq);
    }

    // Zero y regions of both buffers once; halo slots / invalid rows are
    // never rewritten by staging.
    {
        const float4 z = make_float4(0.f, 0.f, 0.f, 0.f);
        #pragma unroll
        for (int nb = 0; nb < NBUF; ++nb) {
            float4* yz = smem + nb * BUF4 + XSZ4;
            for (int idx = tid; idx < YSZ4; idx += NTH) yz[idx] = z;
        }
    }
    __syncthreads();

    float acc[8][PP];
    #pragma unroll
    for (int k = 0; k < 8; ++k)
        #pragma unroll
        for (int d = 0; d < PP; ++d)
            acc[k][d] = 0.0f;

    // Prime
    stage_chunk(smem, xb, yb, 0, i0, tid, vmask);
    cp_commit();

    for (int k = 0; k < NCHUNK; ++k) {
        if (k + 1 < NCHUNK) {
            stage_chunk(smem + ((k + 1) & 1) * BUF4, xb, yb,
                        (k + 1) * KC, i0, tid, vmask);
            cp_commit();
            asm volatile("cp.async.wait_group 1;\n");
        } else {
            asm volatile("cp.async.wait_group 0;\n");
        }
        __syncthreads();
        compute_chunk(smem + (k & 1) * BUF4, acc, xo0, xo1, yo0, yo1, yo2, yo3);
        __syncthreads();
    }

    // Write out: out[b, di*9+d, i0+r, jseg..jseg+7]
    const float scale = 1.0f / (float)CC;
    #pragma unroll
    for (int d = 0; d < PP; ++d) {
        int ch = di * PP + d;
        float* o = out + (((size_t)b * (PP * PP) + ch) * HH + (i0 + r)) * WW + jseg;
        float4 v0, v1;
        v0.x = acc[0][d] * scale; v0.y = acc[1][d] * scale;
        v0.z = acc[2][d] * scale; v0.w = acc[3][d] * scale;
        v1.x = acc[4][d] * scale; v1.y = acc[5][d] * scale;
        v1.z = acc[6][d] * scale; v1.w = acc[7][d] * scale;
        reinterpret_cast<float4*>(o)[0] = v0;
        reinterpret_cast<float4*>(o)[1] = v1;
    }
}

extern "C" void kernel_launch(void* const* d_in, const int* in_sizes, int n_in,
                              void* d_out, int out_size)
{
    const float* x = (const float*)d_in[0];
    const float* y = (const float*)d_in[1];
    float* out = (float*)d_out;
    (void)in_sizes; (void)n_in; (void)out_size;

    cudaFuncSetAttribute(corr_kernel,
                         cudaFuncAttributeMaxDynamicSharedMemorySize, SMEM_BYTES);

    dim3 grid(BB * (HH / TI));   // 256 blocks
    dim3 block(NTH);             // 9 warps
    corr_kernel<<<grid, block, SMEM_BYTES>>>(x, y, out);
}

// round 16
// speedup vs baseline: 1.3962x; 1.3962x over previous
#include <cuda_runtime.h>
#include <cstdint>
#include <cstddef>

// Problem constants
#define BB 16
#define CC 256
#define HH 64
#define WW 64
#define HW (HH*WW)
#define DD 4          // max displacement
#define PP 9          // patch = 2d+1

// Tiling
#define TI 4          // rows per block tile
#define KC 8          // channels per staged chunk
#define NCHUNK (CC/KC)
#define XS 66         // x smem row stride (floats); LDS.64 residues conflict-free
#define YR (TI + 2*DD)   // 12 y rows per tile
#define YS 74         // y smem row stride (floats); LDS.64 residues conflict-free

#define NTH 288       // 9 warps; warp w == displacement row di
#define NBUF 3        // triple buffer -> single barrier per chunk

#define XSZ (KC*TI*XS)     // 2112 floats
#define YSZ (KC*YR*YS)     // 7104 floats
#define BUFSZ (XSZ+YSZ)    // 9216 floats
#define SMEM_BYTES (NBUF*BUFSZ*4)   // 110592 B; x2 blocks/SM = 221 KB

__device__ __forceinline__ uint32_t s2u(const void* p) {
    return (uint32_t)__cvta_generic_to_shared(p);
}
__device__ __forceinline__ void cpa8(uint32_t s, const float* g) {
    asm volatile("cp.async.ca.shared.global [%0], [%1], 8;\n" :: "r"(s), "l"(g));
}
__device__ __forceinline__ void cp_commit() {
    asm volatile("cp.async.commit_group;\n");
}

// Stage one 8-channel chunk into buffer sb. Shift/mask index math only.
__device__ __forceinline__ void stage_chunk(float* sb,
                                            const float* __restrict__ xb,
                                            const float* __restrict__ yb,
                                            int c0, int i0, int tid, int vmask)
{
    // x: KC*TI*32 = 1024 float2 jobs, thread-strided
    for (int idx = tid; idx < KC * TI * 32; idx += NTH) {
        int c    = idx >> 7;
        int rr   = (idx >> 5) & 3;
        int col2 = idx & 31;
        uint32_t s = s2u(sb + c * (TI * XS) + rr * XS + col2 * 2);
        cpa8(s, xb + (size_t)(c0 + c) * HW + (i0 + rr) * WW + col2 * 2);
    }
    // y: 96 row-jobs, one warp per job, 32 f2 per row
    int w = tid >> 5, lane = tid & 31;
    for (int job = w; job < KC * YR; job += 9) {
        int q = job >> 3;
        int c = job & 7;
        if ((vmask >> q) & 1) {
            int gi = i0 + q - DD;
            uint32_t s = s2u(sb + XSZ + c * (YR * YS) + q * YS + DD + lane * 2);
            cpa8(s, yb + (size_t)(c0 + c) * HW + gi * WW + lane * 2);
        }
    }
}

// Compute: 8 columns x 9 dj per thread, 72 scalar FFMA per channel.
// Channel order rotated per warp (rot) to de-phase LDS bursts across warps.
__device__ __forceinline__ void compute_chunk(const float* sb, float acc[8][PP],
                                              int r, int di, int jseg, int rot)
{
    #pragma unroll
    for (int c = 0; c < KC; ++c) {
        int cc = (c + rot) & (KC - 1);
        const float2* xr2 = reinterpret_cast<const float2*>(
            sb + cc * (TI * XS) + r * XS + jseg);
        const float2* yr2 = reinterpret_cast<const float2*>(
            sb + XSZ + cc * (YR * YS) + (r + di) * YS + jseg);

        float xv[8], yv[16];
        #pragma unroll
        for (int m = 0; m < 4; ++m) {
            float2 v = xr2[m];
            xv[2 * m] = v.x; xv[2 * m + 1] = v.y;
        }
        #pragma unroll
        for (int m = 0; m < 8; ++m) {
            float2 v = yr2[m];
            yv[2 * m] = v.x; yv[2 * m + 1] = v.y;
        }
        #pragma unroll
        for (int k = 0; k < 8; ++k)
            #pragma unroll
            for (int d = 0; d < PP; ++d)
                acc[k][d] += xv[k] * yv[k + d];
    }
}

__global__ __launch_bounds__(NTH, 2)
void corr_kernel(const float* __restrict__ x,
                 const float* __restrict__ y,
                 float* __restrict__ out)
{
    extern __shared__ float smem[];   // [NBUF][BUFSZ]

    const int bx   = blockIdx.x;
    const int b    = bx >> 4;
    const int i0   = (bx & 15) * TI;
    const int tid  = threadIdx.x;
    const int di   = tid >> 5;
    const int lane = tid & 31;
    const int r    = lane & 3;
    const int jseg = (lane >> 2) * 8;
    const int rot  = di & (KC - 1);   // per-warp channel rotation

    const float* xb = x + (size_t)b * CC * HW;
    const float* yb = y + (size_t)b * CC * HW;

    // Valid-row mask for the y tile (rows i0-4 .. i0+7)
    int vmask = 0;
    #pragma unroll
    for (int q = 0; q < YR; ++q) {
        int gi = i0 + q - DD;
        if (gi >= 0 && gi < HH) vmask |= (1 << q);
    }

    // Zero the y regions of all buffers once; halo slots never rewritten.
    {
        const float2 z = make_float2(0.f, 0.f);
        #pragma unroll
        for (int nb = 0; nb < NBUF; ++nb) {
            float2* yz = reinterpret_cast<float2*>(smem + nb * BUFSZ + XSZ);
            for (int idx = tid; idx < YSZ / 2; idx += NTH) yz[idx] = z;
        }
    }
    __syncthreads();

    float acc[8][PP];
    #pragma unroll
    for (int k = 0; k < 8; ++k)
        #pragma unroll
        for (int d = 0; d < PP; ++d)
            acc[k][d] = 0.0f;

    // Prime two chunks
    stage_chunk(smem + 0 * BUFSZ, xb, yb, 0, i0, tid, vmask);
    cp_commit();
    stage_chunk(smem + 1 * BUFSZ, xb, yb, KC, i0, tid, vmask);
    cp_commit();

    // wait(k) -> sync -> compute(k) -> stage(k+2): stage writes buf (k-1)%3;
    // every thread is past sync(k), which follows its compute(k-1) reads of
    // that buffer. One barrier per chunk. (Ordering proven in R5/R8.)
    int cur = 0, nxt = 2;
    for (int k = 0; k < NCHUNK; ++k) {
        if (k + 1 < NCHUNK) {
            asm volatile("cp.async.wait_group 1;\n");   // chunk k's group done
        } else {
            asm volatile("cp.async.wait_group 0;\n");
        }
        __syncthreads();
        compute_chunk(smem + cur * BUFSZ, acc, r, di, jseg, rot);
        if (k + 2 < NCHUNK) {
            stage_chunk(smem + nxt * BUFSZ, xb, yb, (k + 2) * KC, i0, tid, vmask);
            cp_commit();
        }
        cur = (cur + 1 == NBUF) ? 0 : cur + 1;
        nxt = (nxt + 1 == NBUF) ? 0 : nxt + 1;
    }

    // Write out: out[b, di*9+d, i0+r, jseg..jseg+7]
    const float scale = 1.0f / (float)CC;
    #pragma unroll
    for (int d = 0; d < PP; ++d) {
        int ch = di * PP + d;
        float* o = out + (((size_t)b * (PP * PP) + ch) * HH + (i0 + r)) * WW + jseg;
        float4 v0, v1;
        v0.x = acc[0][d] * scale; v0.y = acc[1][d] * scale;
        v0.z = acc[2][d] * scale; v0.w = acc[3][d] * scale;
        v1.x = acc[4][d] * scale; v1.y = acc[5][d] * scale;
        v1.z = acc[6][d] * scale; v1.w = acc[7][d] * scale;
        reinterpret_cast<float4*>(o)[0] = v0;
        reinterpret_cast<float4*>(o)[1] = v1;
    }
}

extern "C" void kernel_launch(void* const* d_in, const int* in_sizes, int n_in,
                              void* d_out, int out_size)
{
    const float* x = (const float*)d_in[0];
    const float* y = (const float*)d_in[1];
    float* out = (float*)d_out;
    (void)in_sizes; (void)n_in; (void)out_size;

    cudaFuncSetAttribute(corr_kernel,
                         cudaFuncAttributeMaxDynamicSharedMemorySize, SMEM_BYTES);

    dim3 grid(BB * (HH / TI));   // 256 blocks
    dim3 block(NTH);             // 9 warps
    corr_kernel<<<grid, block, SMEM_BYTES>>>(x, y, out);
}

// round 17
// speedup vs baseline: 1.6335x; 1.1700x over previous
#include <cuda_runtime.h>
#include <cstdint>
#include <cstddef>

// Problem constants
#define BB 16
#define CC 256
#define HH 64
#define WW 64
#define HW (HH*WW)
#define DD 4          // max displacement
#define PP 9          // patch = 2d+1

// Tiling
#define TI 4          // rows per block tile
#define KC 8          // channels per staged chunk
#define NCHUNK (CC/KC)
#define XS 66         // x smem row stride (floats); LDS.64 residues conflict-free
#define YR (TI + 2*DD)   // 12 y rows per tile
#define YS 74         // y smem row stride (floats); LDS.64 residues conflict-free

#define NTH 288       // 9 warps; warp w == displacement row di
#define NBUF 3        // triple buffer -> single barrier per chunk
#define NYJOB 11      // max y jobs per warp (96 jobs / 9 warps, ceil)

#define XSZ (KC*TI*XS)     // 2112 floats
#define YSZ (KC*YR*YS)     // 7104 floats
#define BUFSZ (XSZ+YSZ)    // 9216 floats
#define SMEM_BYTES (NBUF*BUFSZ*4)   // 110592 B dynamic; + ~0.8 KB static table

__device__ __forceinline__ uint32_t s2u(const void* p) {
    return (uint32_t)__cvta_generic_to_shared(p);
}
__device__ __forceinline__ void cpa8(uint32_t s, const void* g) {
    asm volatile("cp.async.ca.shared.global [%0], [%1], 8;\n" :: "r"(s), "l"(g));
}
__device__ __forceinline__ void cp_commit() {
    asm volatile("cp.async.commit_group;\n");
}

// Stage one 8-channel chunk into buffer sb.
// x: shift/mask math (cheap). y: precomputed compacted job table.
__device__ __forceinline__ void stage_chunk(float* sb,
                                            const float* __restrict__ xb,
                                            const char*  __restrict__ yg,   // yb + c0*HW floats
                                            int c0, int i0, int tid,
                                            const uint2* __restrict__ yjob, // this warp's table
                                            int nj, int lane8)
{
    // x: KC*TI*32 = 1024 float2 jobs, thread-strided
    for (int idx = tid; idx < KC * TI * 32; idx += NTH) {
        int c    = idx >> 7;
        int rr   = (idx >> 5) & 3;
        int col2 = idx & 31;
        uint32_t s = s2u(sb + c * (TI * XS) + rr * XS + col2 * 2);
        cpa8(s, xb + (size_t)(c0 + c) * HW + (i0 + rr) * WW + col2 * 2);
    }
    // y: compacted valid jobs; each job = one 64-float row, 32 lanes x 8B
    uint32_t ysm = s2u(sb + XSZ) + (uint32_t)lane8;
    for (int t = 0; t < nj; ++t) {
        uint2 jb = yjob[t];                 // broadcast LDS.64
        cpa8(ysm + jb.x, yg + jb.y + lane8);
    }
}

// Compute: 8 columns x 9 dj per thread, 72 scalar FFMA per channel.
__device__ __forceinline__ void compute_chunk(const float* sb, float acc[8][PP],
                                              int r, int di, int jseg)
{
    #pragma unroll
    for (int c = 0; c < KC; ++c) {
        const float2* xr2 = reinterpret_cast<const float2*>(
            sb + c * (TI * XS) + r * XS + jseg);
        const float2* yr2 = reinterpret_cast<const float2*>(
            sb + XSZ + c * (YR * YS) + (r + di) * YS + jseg);

        float xv[8], yv[16];
        #pragma unroll
        for (int m = 0; m < 4; ++m) {
            float2 v = xr2[m];
            xv[2 * m] = v.x; xv[2 * m + 1] = v.y;
        }
        #pragma unroll
        for (int m = 0; m < 8; ++m) {
            float2 v = yr2[m];
            yv[2 * m] = v.x; yv[2 * m + 1] = v.y;
        }
        #pragma unroll
        for (int k = 0; k < 8; ++k)
            #pragma unroll
            for (int d = 0; d < PP; ++d)
                acc[k][d] += xv[k] * yv[k + d];
    }
}

__global__ __launch_bounds__(NTH, 2)
void corr_kernel(const float* __restrict__ x,
                 const float* __restrict__ y,
                 float* __restrict__ out)
{
    extern __shared__ float smem[];            // [NBUF][BUFSZ]
    __shared__ uint2 yjob[9][NYJOB];           // compacted y staging jobs
    __shared__ int   yjn[9];                   // valid job count per warp

    const int bx   = blockIdx.x;
    const int b    = bx >> 4;
    const int i0   = (bx & 15) * TI;
    const int tid  = threadIdx.x;
    const int di   = tid >> 5;
    const int lane = tid & 31;
    const int r    = lane & 3;
    const int jseg = (lane >> 2) * 8;
    const int lane8 = lane * 8;                // byte offset of this lane's f2

    const float* xb = x + (size_t)b * CC * HW;
    const float* yb = y + (size_t)b * CC * HW;

    // Build this warp's compacted y-job table (lane 0 only).
    if (lane == 0) {
        int n = 0;
        for (int job = di; job < KC * YR; job += 9) {
            int q = job >> 3;
            int c = job & 7;
            int gi = i0 + q - DD;
            if (gi >= 0 && gi < HH) {
                yjob[di][n].x = (uint32_t)((c * (YR * YS) + q * YS + DD) * 4);
                yjob[di][n].y = (uint32_t)((c * HW + gi * WW) * 4);
                ++n;
            }
        }
        yjn[di] = n;
    }

    // Zero the y regions of all buffers once; halo slots / invalid rows are
    // never rewritten by staging (compacted table skips them).
    {
        const float2 z = make_float2(0.f, 0.f);
        #pragma unroll
        for (int nb = 0; nb < NBUF; ++nb) {
            float2* yz = reinterpret_cast<float2*>(smem + nb * BUFSZ + XSZ);
            for (int idx = tid; idx < YSZ / 2; idx += NTH) yz[idx] = z;
        }
    }
    __syncthreads();   // table + zeroed buffers visible

    const int nj = yjn[di];
    const uint2* myjobs = yjob[di];
    const char* ygbase = (const char*)yb;

    float acc[8][PP];
    #pragma unroll
    for (int k = 0; k < 8; ++k)
        #pragma unroll
        for (int d = 0; d < PP; ++d)
            acc[k][d] = 0.0f;

    // Prime two chunks
    stage_chunk(smem + 0 * BUFSZ, xb, ygbase, 0, i0, tid, myjobs, nj, lane8);
    cp_commit();
    stage_chunk(smem + 1 * BUFSZ, xb, ygbase + (size_t)KC * HW * 4, KC, i0, tid,
                myjobs, nj, lane8);
    cp_commit();

    // wait(k) -> sync -> compute(k) -> stage(k+2): stage writes buf (k-1)%3;
    // every thread is past sync(k), which follows its compute(k-1) reads of
    // that buffer. One barrier per chunk. (Ordering proven in R5/R8.)
    int cur = 0, nxt = 2;
    for (int k = 0; k < NCHUNK; ++k) {
        if (k + 1 < NCHUNK) {
            asm volatile("cp.async.wait_group 1;\n");   // chunk k's group done
        } else {
            asm volatile("cp.async.wait_group 0;\n");
        }
        __syncthreads();
        compute_chunk(smem + cur * BUFSZ, acc, r, di, jseg);
        if (k + 2 < NCHUNK) {
            stage_chunk(smem + nxt * BUFSZ, xb,
                        ygbase + (size_t)(k + 2) * KC * HW * 4, (k + 2) * KC,
                        i0, tid, myjobs, nj, lane8);
            cp_commit();
        }
        cur = (cur + 1 == NBUF) ? 0 : cur + 1;
        nxt = (nxt + 1 == NBUF) ? 0 : nxt + 1;
    }

    // Write out: out[b, di*9+d, i0+r, jseg..jseg+7]
    const float scale = 1.0f / (float)CC;
    #pragma unroll
    for (int d = 0; d < PP; ++d) {
        int ch = di * PP + d;
        float* o = out + (((size_t)b * (PP * PP) + ch) * HH + (i0 + r)) * WW + jseg;
        float4 v0, v1;
        v0.x = acc[0][d] * scale; v0.y = acc[1][d] * scale;
        v0.z = acc[2][d] * scale; v0.w = acc[3][d] * scale;
        v1.x = acc[4][d] * scale; v1.y = acc[5][d] * scale;
        v1.z = acc[6][d] * scale; v1.w = acc[7][d] * scale;
        reinterpret_cast<float4*>(o)[0] = v0;
        reinterpret_cast<float4*>(o)[1] = v1;
    }
}

extern "C" void kernel_launch(void* const* d_in, const int* in_sizes, int n_in,
                              void* d_out, int out_size)
{
    const float* x = (const float*)d_in[0];
    const float* y = (const float*)d_in[1];
    float* out = (float*)d_out;
    (void)in_sizes; (void)n_in; (void)out_size;

    cudaFuncSetAttribute(corr_kernel,
                         cudaFuncAttributeMaxDynamicSharedMemorySize, SMEM_BYTES);

    dim3 grid(BB * (HH / TI));   // 256 blocks
    dim3 block(NTH);             // 9 warps
    corr_kernel<<<grid, block, SMEM_BYTES>>>(x, y, out);
}